// round 3
// baseline (speedup 1.0000x reference)
#include <cuda_runtime.h>
#include <cuda_bf16.h>
#include <math.h>

#define NB 128
#define NC 32
#define HW 16
#define NE 4096
#define FSZ (NB*NC*HW*HW)   // 1048576

static const int h_PNS[10] = {1,2,3,4,5,6,8,10,13,16};

// ---------------- scratch (device globals; no allocation) ----------------
__device__ float g_cbn[NE*NC];        // normalized codebook
__device__ float g_frest[FSZ];        // residual
__device__ float g_x[FSZ];            // tokens [ntok][32]
__device__ int   g_idx[NB*256];       // chosen code per token
__device__ float g_pv[65536];         // partial argmax values
__device__ int   g_pi[65536];         // partial argmax indices
__device__ int   g_hist[NE];          // last-scale histogram
__device__ float g_part[10*NB];       // per (scale, b) sum of squares

// ---------------- init: f_rest <- f_input, zero out/hist ----------------
__global__ void k_init(const float* __restrict__ fin, float* __restrict__ out,
                       int out_size) {
    int i = blockIdx.x * 256 + threadIdx.x;
    if (i < FSZ) g_frest[i] = fin[i];
    if (i < NE)  g_hist[i] = 0;
    if (i < out_size) out[i] = 0.0f;
}

// ---------------- normalize codebook ----------------
__global__ void k_cbnorm(const float* __restrict__ cb) {
    int i = blockIdx.x * 256 + threadIdx.x;
    if (i >= NE) return;
    const float* r = cb + (size_t)i * NC;
    float s = 0.f;
#pragma unroll
    for (int c = 0; c < NC; c++) s += r[c] * r[c];
    float d = fmaxf(sqrtf(s), 1e-12f);
    float inv = 1.0f / d;
    float* w = g_cbn + (size_t)i * NC;
#pragma unroll
    for (int c = 0; c < NC; c++) w[c] = r[c] * inv;
}

// ---------------- area downsample f_rest -> tokens [ntok][C] ----------------
__global__ void k_down(int pn) {
    int t = blockIdx.x * 256 + threadIdx.x;
    int pnpn = pn * pn;
    int ntot = NB * pnpn * NC;
    if (t >= ntot) return;
    int c = t & 31, token = t >> 5;
    int b = token / pnpn, p = token - b * pnpn;
    int py = p / pn, px = p - py * pn;
    int ys = (py * HW) / pn, ye = ((py + 1) * HW + pn - 1) / pn;
    int xs = (px * HW) / pn, xe = ((px + 1) * HW + pn - 1) / pn;
    const float* base = g_frest + ((size_t)(b * NC + c)) * (HW * HW);
    float s = 0.f;
    for (int y = ys; y < ye; y++)
        for (int x = xs; x < xe; x++) s += base[y * HW + x];
    g_x[(size_t)token * NC + c] = s / (float)((ye - ys) * (xe - xs));
}

// ---------------- argmax over codes (thread handles 2 tokens) ----------------
// grid = (ceil(ntok/256), CS), block = 128. cpb = 4096/CS (multiple of 128).
__global__ __launch_bounds__(128) void k_argmax(int ntok, int cpb) {
    __shared__ float s_cb[128 * NC];
    int tid = threadIdx.x;
    int cs = blockIdx.y;
    int cbase = cs * cpb;
    int t0 = blockIdx.x * 256 + tid;
    int t1 = t0 + 128;
    bool va = t0 < ntok, vb = t1 < ntok;

    float ta[NC], tb[NC];
#pragma unroll
    for (int i = 0; i < NC; i++) { ta[i] = 0.f; tb[i] = 0.f; }
    if (va) {
        const float4* p = (const float4*)(g_x + (size_t)t0 * NC);
#pragma unroll
        for (int i = 0; i < 8; i++) {
            float4 v = p[i];
            ta[i*4+0]=v.x; ta[i*4+1]=v.y; ta[i*4+2]=v.z; ta[i*4+3]=v.w;
        }
    }
    if (vb) {
        const float4* p = (const float4*)(g_x + (size_t)t1 * NC);
#pragma unroll
        for (int i = 0; i < 8; i++) {
            float4 v = p[i];
            tb[i*4+0]=v.x; tb[i*4+1]=v.y; tb[i*4+2]=v.z; tb[i*4+3]=v.w;
        }
    }

    float bva = -3.4e38f, bvb = -3.4e38f;
    int bia = 0, bib = 0;

    for (int tilebase = 0; tilebase < cpb; tilebase += 128) {
        __syncthreads();
        {
            const float4* src = (const float4*)(g_cbn + (size_t)(cbase + tilebase) * NC);
            float4* dst = (float4*)s_cb;
            for (int i = tid; i < 128 * 8; i += 128) dst[i] = src[i];
        }
        __syncthreads();
#pragma unroll 2
        for (int j = 0; j < 128; j++) {
            const float4* cr = (const float4*)(s_cb + j * NC);
            float a0=0,a1=0,a2=0,a3=0,b0=0,b1=0,b2=0,b3=0;
#pragma unroll
            for (int q = 0; q < 8; q++) {
                float4 cv = cr[q];
                a0 = fmaf(cv.x, ta[q*4+0], a0);
                a1 = fmaf(cv.y, ta[q*4+1], a1);
                a2 = fmaf(cv.z, ta[q*4+2], a2);
                a3 = fmaf(cv.w, ta[q*4+3], a3);
                b0 = fmaf(cv.x, tb[q*4+0], b0);
                b1 = fmaf(cv.y, tb[q*4+1], b1);
                b2 = fmaf(cv.z, tb[q*4+2], b2);
                b3 = fmaf(cv.w, tb[q*4+3], b3);
            }
            float da = (a0+a1)+(a2+a3);
            float db = (b0+b1)+(b2+b3);
            int code = cbase + tilebase + j;
            if (da > bva) { bva = da; bia = code; }
            if (db > bvb) { bvb = db; bib = code; }
        }
    }
    int CS = gridDim.y;
    if (va) { g_pv[(size_t)t0 * CS + cs] = bva; g_pi[(size_t)t0 * CS + cs] = bia; }
    if (vb) { g_pv[(size_t)t1 * CS + cs] = bvb; g_pi[(size_t)t1 * CS + cs] = bib; }
}

// ---------------- combine code-split partials (min-index tie-break) ----------------
__global__ void k_combine(int ntok, int CS) {
    int t = blockIdx.x * 256 + threadIdx.x;
    if (t >= ntok) return;
    float bv = g_pv[(size_t)t * CS];
    int bi = g_pi[(size_t)t * CS];
    for (int cs = 1; cs < CS; cs++) {
        float v = g_pv[(size_t)t * CS + cs];
        int i = g_pi[(size_t)t * CS + cs];
        if (v > bv || (v == bv && i < bi)) { bv = v; bi = i; }
    }
    g_idx[t] = bi;
}

// ---------------- histogram of last-scale codes ----------------
__global__ void k_hist(int ntok) {
    int t = blockIdx.x * 256 + threadIdx.x;
    if (t < ntok) atomicAdd(&g_hist[g_idx[t]], 1);
}

// -------- fused: gather codes -> bicubic upsample -> 3x3 conv (Phi) -> update --------
// one block per batch image b; 256 threads. smem = 111904 bytes.
#define SW_OFF   0
#define SB_OFF   9216
#define HUP_OFF  (9216+32)
#define HS_OFF   (HUP_OFF+10400)
#define WT_OFF   (HS_OFF+8192)
#define JT_OFF   (WT_OFF+64)
#define RED_OFF  (JT_OFF+64)
#define SMEM_FLOATS (RED_OFF+8)

__global__ __launch_bounds__(256) void k_fused(
    const float* __restrict__ fin, float* __restrict__ fhat,
    const float* __restrict__ cb, const float* __restrict__ phiw,
    const float* __restrict__ phib, int si, int pn, int k, int last) {
    extern __shared__ float sm[];
    float* s_w   = sm + SW_OFF;
    float* s_b   = sm + SB_OFF;
    float* s_hup = sm + HUP_OFF;   // [32][325] (18x18 halo, padded stride)
    float* s_hs  = sm + HS_OFF;    // [p][c]
    float* s_wt  = sm + WT_OFF;    // bicubic weights [16][4]
    int*   s_jt  = (int*)(sm + JT_OFF);
    float* s_red = sm + RED_OFF;

    int tid = threadIdx.x;
    int b = blockIdx.x;
    int pnpn = pn * pn;

    // load Phi weights/bias
    {
        const float4* wsrc = (const float4*)(phiw + (size_t)k * 9216);
        float4* wdst = (float4*)s_w;
        for (int i = tid; i < 2304; i += 256) wdst[i] = wsrc[i];
        if (tid < 32) s_b[tid] = phib[k * 32 + tid];
    }
    // zero halo image
    for (int i = tid; i < 10400; i += 256) s_hup[i] = 0.f;

    if (!last) {
        if (tid < 64) {
            int i = tid >> 2, off = (tid & 3) - 1;
            double src = (i + 0.5) * (double)pn / 16.0 - 0.5;
            double i0 = floor(src);
            double f = src - i0;
            double t = fabs(f - (double)off);
            double w;
            if (t <= 1.0)      w = (1.25 * t - 2.25) * t * t + 1.0;
            else if (t < 2.0)  w = (((t - 5.0) * t + 8.0) * t - 4.0) * (-0.75);
            else               w = 0.0;
            int j = (int)i0 + off;
            j = min(max(j, 0), pn - 1);
            s_wt[tid] = (float)w;
            s_jt[tid] = j;
        }
        for (int t = tid; t < pnpn * 32; t += 256) {
            int p = t >> 5, c = t & 31;
            s_hs[t] = cb[(size_t)g_idx[b * pnpn + p] * NC + c];
        }
    }
    __syncthreads();

    // build h_up (interior of halo'd image)
    if (last) {
        for (int o = tid; o < 8192; o += 256) {
            int c = o & 31, pix = o >> 5;
            int y = pix >> 4, x = pix & 15;
            s_hup[c * 325 + (y + 1) * 18 + (x + 1)] =
                cb[(size_t)g_idx[b * 256 + pix] * NC + c];
        }
    } else {
        for (int o = tid; o < 8192; o += 256) {
            int c = o & 31, pix = o >> 5;
            int y = pix >> 4, x = pix & 15;
            float acc = 0.f;
#pragma unroll
            for (int ty = 0; ty < 4; ty++) {
                float wy = s_wt[y * 4 + ty];
                int jy = s_jt[y * 4 + ty];
                const float* row = s_hs + (jy * pn) * 32 + c;
                float rs = 0.f;
#pragma unroll
                for (int tx = 0; tx < 4; tx++)
                    rs = fmaf(s_wt[x * 4 + tx], row[s_jt[x * 4 + tx] * 32], rs);
                acc = fmaf(wy, rs, acc);
            }
            s_hup[c * 325 + (y + 1) * 18 + (x + 1)] = acc;
        }
    }
    __syncthreads();

    // 3x3 conv: warp wi owns co in [4wi, 4wi+4); lane -> (y = lane>>1, xs = (lane&1)*8)
    int wi = tid >> 5, lane = tid & 31;
    int y = lane >> 1, xs = (lane & 1) * 8;
    float acc[4][8];
#pragma unroll
    for (int a = 0; a < 4; a++)
#pragma unroll
        for (int o = 0; o < 8; o++) acc[a][o] = 0.f;

    for (int ci = 0; ci < 32; ci++) {
        float tp[3][10];
        const float* hp = s_hup + ci * 325 + y * 18 + xs;
#pragma unroll
        for (int r = 0; r < 3; r++)
#pragma unroll
            for (int cc = 0; cc < 10; cc++) tp[r][cc] = hp[r * 18 + cc];
#pragma unroll
        for (int co4 = 0; co4 < 4; co4++) {
            const float* wp = s_w + ((size_t)(wi * 4 + co4) * 32 + ci) * 9;
            float w0 = wp[0], w1 = wp[1], w2 = wp[2];
            float w3 = wp[3], w4 = wp[4], w5 = wp[5];
            float w6 = wp[6], w7 = wp[7], w8 = wp[8];
#pragma unroll
            for (int xo = 0; xo < 8; xo++) {
                float s = acc[co4][xo];
                s = fmaf(w0, tp[0][xo],     s);
                s = fmaf(w1, tp[0][xo + 1], s);
                s = fmaf(w2, tp[0][xo + 2], s);
                s = fmaf(w3, tp[1][xo],     s);
                s = fmaf(w4, tp[1][xo + 1], s);
                s = fmaf(w5, tp[1][xo + 2], s);
                s = fmaf(w6, tp[2][xo],     s);
                s = fmaf(w7, tp[2][xo + 1], s);
                s = fmaf(w8, tp[2][xo + 2], s);
                acc[co4][xo] = s;
            }
        }
    }

    // h = 0.5*h_up + 0.5*(conv + bias); update f_hat, f_rest; accumulate MSE
    float sq = 0.f;
    const float* finb = fin + (size_t)b * 8192;
    float* fhb = fhat + (size_t)b * 8192;
    float* frb = g_frest + (size_t)b * 8192;
#pragma unroll
    for (int co4 = 0; co4 < 4; co4++) {
        int co = wi * 4 + co4;
        float bias = s_b[co];
#pragma unroll
        for (int xo = 0; xo < 8; xo++) {
            int x = xs + xo;
            float conv = acc[co4][xo] + bias;
            float hu = s_hup[co * 325 + (y + 1) * 18 + (x + 1)];
            float h = 0.5f * hu + 0.5f * conv;
            int g = co * 256 + y * 16 + x;
            float fh = fhb[g] + h;
            fhb[g] = fh;
            frb[g] = frb[g] - h;
            float d = fh - finb[g];
            sq = fmaf(d, d, sq);
        }
    }
#pragma unroll
    for (int o = 16; o; o >>= 1) sq += __shfl_down_sync(0xffffffffu, sq, o);
    if (lane == 0) s_red[wi] = sq;
    __syncthreads();
    if (tid == 0) {
        float s = 0.f;
        for (int i = 0; i < 8; i++) s += s_red[i];
        g_part[si * NB + b] = s;
    }
}

// ---------------- finalize: loss + perplexity ----------------
__global__ void k_final(float* __restrict__ out, int out_size) {
    __shared__ float sr[256];
    int tid = threadIdx.x;
    float s = 0.f;
    for (int i = tid; i < 10 * NB; i += 256) s += g_part[i];
    sr[tid] = s;
    __syncthreads();
    for (int o = 128; o; o >>= 1) {
        if (tid < o) sr[tid] += sr[tid + o];
        __syncthreads();
    }
    float lossv = 0.f;
    if (tid == 0) lossv = sr[0] * (1.25f / (10.0f * (float)FSZ));
    __syncthreads();

    float e = 0.f;
    for (int i = tid; i < NE; i += 256) {
        float p = (float)g_hist[i] * (1.0f / 32768.0f);
        e += p * logf(p + 1e-10f);
    }
    sr[tid] = e;
    __syncthreads();
    for (int o = 128; o; o >>= 1) {
        if (tid < o) sr[tid] += sr[tid + o];
        __syncthreads();
    }
    if (tid == 0) {
        out[out_size - 2] = lossv;
        out[out_size - 1] = expf(-sr[0]);
    }
}

// ---------------- launcher ----------------
extern "C" void kernel_launch(void* const* d_in, const int* in_sizes, int n_in,
                              void* d_out, int out_size) {
    // Identify inputs BY SIZE (robust to metadata ordering):
    //   f_input 1048576, codebook 131072, phi_w 36864, phi_b 128
    const float* fin  = nullptr;
    const float* cb   = nullptr;
    const float* phiw = nullptr;
    const float* phib = nullptr;
    for (int i = 0; i < n_in; i++) {
        int sz = in_sizes[i];
        if      (sz == FSZ)        fin  = (const float*)d_in[i];
        else if (sz == NE * NC)    cb   = (const float*)d_in[i];
        else if (sz == 4*NC*NC*9)  phiw = (const float*)d_in[i];
        else if (sz == 4*NC)       phib = (const float*)d_in[i];
    }
    float* out = (float*)d_out;

    // PhiPartiallyShared tick schedule, replicating numpy float64 exactly:
    // ticks = linspace(1/12, 1-1/12, 4): step=(stop-start)/3,
    // tick_i = fl(fl(i*step)+start), tick_3 = stop; argmin(|ticks-v|) first-tie.
    int phik[10];
    {
        double start = 1.0 / 12.0;
        double stop  = 1.0 - 1.0 / 12.0;
        double step  = (stop - start) / 3.0;
        double ticks[4];
        ticks[0] = start;
        ticks[1] = 1.0 * step + start;
        ticks[2] = 2.0 * step + start;
        ticks[3] = stop;
        for (int si = 0; si < 10; si++) {
            double v = (double)si / 9.0;
            int best = 0;
            double bd = fabs(ticks[0] - v);
            for (int kk = 1; kk < 4; kk++) {
                double d = fabs(ticks[kk] - v);
                if (d < bd) { bd = d; best = kk; }
            }
            phik[si] = best;
        }
    }

    cudaFuncSetAttribute(k_fused, cudaFuncAttributeMaxDynamicSharedMemorySize,
                         SMEM_FLOATS * 4);

    int initN = (FSZ > out_size ? FSZ : out_size);
    k_init<<<(initN + 255) / 256, 256>>>(fin, out, out_size);
    k_cbnorm<<<(NE + 255) / 256, 256>>>(cb);

    for (int si = 0; si < 10; si++) {
        int pn = h_PNS[si];
        int ntok = NB * pn * pn;
        int last = (si == 9);

        k_down<<<(ntok * NC + 255) / 256, 256>>>(pn);

        int tb = (ntok + 255) / 256;
        int CS = 1;
        while (tb * CS < 120 && CS < 32) CS <<= 1;
        dim3 g(tb, CS);
        k_argmax<<<g, 128>>>(ntok, NE / CS);
        k_combine<<<(ntok + 255) / 256, 256>>>(ntok, CS);
        if (last) k_hist<<<(ntok + 255) / 256, 256>>>(ntok);

        k_fused<<<NB, 256, SMEM_FLOATS * 4>>>(fin, out, cb, phiw, phib,
                                              si, pn, phik[si], last);
    }
    k_final<<<1, 256>>>(out, out_size);
}

// round 4
// speedup vs baseline: 1.3540x; 1.3540x over previous
#include <cuda_runtime.h>
#include <cuda_bf16.h>
#include <math.h>

#define NB 128
#define NC 32
#define HW 16
#define NE 4096
#define FSZ (NB*NC*HW*HW)   // 1048576
#define PVCAP (256*1024)

typedef unsigned long long u64;

static const int h_PNS[10] = {1,2,3,4,5,6,8,10,13,16};

// ---------------- scratch (device globals; no allocation) ----------------
__device__ float g_cbn[NE*NC];        // normalized codebook
__device__ float g_frest[FSZ];        // residual
__device__ float g_x[FSZ];            // tokens [ntok][32]
__device__ int   g_idx[NB*256];       // chosen code per token
__device__ float g_pv[PVCAP];         // partial argmax values
__device__ int   g_pi[PVCAP];         // partial argmax indices
__device__ int   g_hist[NE];          // last-scale histogram
__device__ float g_part[10*NB];       // per (scale, b) sum of squares

__device__ __forceinline__ u64 ffma2(u64 a, u64 b, u64 c) {
    u64 d; asm("fma.rn.f32x2 %0, %1, %2, %3;" : "=l"(d) : "l"(a), "l"(b), "l"(c));
    return d;
}
__device__ __forceinline__ u64 fadd2(u64 a, u64 b) {
    u64 d; asm("add.rn.f32x2 %0, %1, %2;" : "=l"(d) : "l"(a), "l"(b));
    return d;
}

// ---------------- init: f_rest <- f_input, zero out/hist ----------------
__global__ void k_init(const float* __restrict__ fin, float* __restrict__ out,
                       int out_size) {
    int i = blockIdx.x * 256 + threadIdx.x;
    if (i < FSZ) g_frest[i] = fin[i];
    if (i < NE)  g_hist[i] = 0;
    if (i < out_size) out[i] = 0.0f;
}

// ---------------- normalize codebook ----------------
__global__ void k_cbnorm(const float* __restrict__ cb) {
    int i = blockIdx.x * 256 + threadIdx.x;
    if (i >= NE) return;
    const float* r = cb + (size_t)i * NC;
    float s = 0.f;
#pragma unroll
    for (int c = 0; c < NC; c++) s += r[c] * r[c];
    float d = fmaxf(sqrtf(s), 1e-12f);
    float inv = 1.0f / d;
    float* w = g_cbn + (size_t)i * NC;
#pragma unroll
    for (int c = 0; c < NC; c++) w[c] = r[c] * inv;
}

// ---------------- area downsample f_rest -> tokens [ntok][C] ----------------
__global__ void k_down(int pn) {
    int t = blockIdx.x * 256 + threadIdx.x;
    int pnpn = pn * pn;
    int ntot = NB * pnpn * NC;
    if (t >= ntot) return;
    int c = t & 31, token = t >> 5;
    int b = token / pnpn, p = token - b * pnpn;
    int py = p / pn, px = p - py * pn;
    int ys = (py * HW) / pn, ye = ((py + 1) * HW + pn - 1) / pn;
    int xs = (px * HW) / pn, xe = ((px + 1) * HW + pn - 1) / pn;
    const float* base = g_frest + ((size_t)(b * NC + c)) * (HW * HW);
    float s = 0.f;
    for (int y = ys; y < ye; y++)
        for (int x = xs; x < xe; x++) s += base[y * HW + x];
    g_x[(size_t)token * NC + c] = s / (float)((ye - ys) * (xe - xs));
}

// ---------------- argmax over codes (f32x2 packed; thread handles 2 tokens) ----
// grid = (ceil(ntok/256), CS), block = 128. cpb = 4096/CS (multiple of 128).
__global__ __launch_bounds__(128) void k_argmax(int ntok, int cpb) {
    __shared__ float s_cb[128 * NC];
    int tid = threadIdx.x;
    int cbase = blockIdx.y * cpb;
    int t0 = blockIdx.x * 256 + tid;
    int t1 = t0 + 128;
    bool va = t0 < ntok, vb = t1 < ntok;

    u64 ta[16], tb[16];
#pragma unroll
    for (int i = 0; i < 16; i++) { ta[i] = 0ULL; tb[i] = 0ULL; }
    if (va) {
        const ulonglong2* p = (const ulonglong2*)(g_x + (size_t)t0 * NC);
#pragma unroll
        for (int i = 0; i < 8; i++) { ulonglong2 v = p[i]; ta[2*i] = v.x; ta[2*i+1] = v.y; }
    }
    if (vb) {
        const ulonglong2* p = (const ulonglong2*)(g_x + (size_t)t1 * NC);
#pragma unroll
        for (int i = 0; i < 8; i++) { ulonglong2 v = p[i]; tb[2*i] = v.x; tb[2*i+1] = v.y; }
    }

    float bva = -3.4e38f, bvb = -3.4e38f;
    int bia = cbase, bib = cbase;

    for (int tilebase = 0; tilebase < cpb; tilebase += 128) {
        __syncthreads();
        {
            const float4* src = (const float4*)(g_cbn + (size_t)(cbase + tilebase) * NC);
            float4* dst = (float4*)s_cb;
            for (int i = tid; i < 128 * 8; i += 128) dst[i] = src[i];
        }
        __syncthreads();
        for (int j = 0; j < 128; j++) {
            const ulonglong2* cr = (const ulonglong2*)(s_cb + j * NC);
            u64 p0 = 0ULL, p1 = 0ULL, q0 = 0ULL, q1 = 0ULL;
#pragma unroll
            for (int i = 0; i < 8; i++) {
                ulonglong2 c = cr[i];
                p0 = ffma2(c.x, ta[2*i],     p0);
                p1 = ffma2(c.y, ta[2*i + 1], p1);
                q0 = ffma2(c.x, tb[2*i],     q0);
                q1 = ffma2(c.y, tb[2*i + 1], q1);
            }
            u64 ps = fadd2(p0, p1);
            u64 qs = fadd2(q0, q1);
            float2 pf = *(float2*)&ps;
            float2 qf = *(float2*)&qs;
            float da = pf.x + pf.y;
            float db = qf.x + qf.y;
            int code = cbase + tilebase + j;
            if (da > bva) { bva = da; bia = code; }
            if (db > bvb) { bvb = db; bib = code; }
        }
    }
    int CS = gridDim.y;
    int cs = blockIdx.y;
    if (va) { g_pv[(size_t)t0 * CS + cs] = bva; g_pi[(size_t)t0 * CS + cs] = bia; }
    if (vb) { g_pv[(size_t)t1 * CS + cs] = bvb; g_pi[(size_t)t1 * CS + cs] = bib; }
}

// ---------------- small-scale argmax: one warp per token ----------------
// grid = (ceil(ntok/4), CS), block = 128 (4 warps).
__global__ __launch_bounds__(128) void k_argmax_small(int ntok, int cpb) {
    int tid = threadIdx.x;
    int wid = tid >> 5, lane = tid & 31;
    int t = blockIdx.x * 4 + wid;
    if (t >= ntok) return;   // whole warp exits together
    int cbase = blockIdx.y * cpb;
    int CS = gridDim.y;

    float tk[32];
    const float4* tp = (const float4*)(g_x + (size_t)t * NC);
#pragma unroll
    for (int i = 0; i < 8; i++) {
        float4 v = tp[i];
        tk[4*i] = v.x; tk[4*i+1] = v.y; tk[4*i+2] = v.z; tk[4*i+3] = v.w;
    }

    float bv = -3.4e38f; int bi = cbase + lane;
    for (int c = cbase + lane; c < cbase + cpb; c += 32) {
        const float4* cr = (const float4*)(g_cbn + (size_t)c * NC);
        float s0 = 0.f, s1 = 0.f, s2 = 0.f, s3 = 0.f;
#pragma unroll
        for (int i = 0; i < 8; i++) {
            float4 v = cr[i];
            s0 = fmaf(v.x, tk[4*i],   s0);
            s1 = fmaf(v.y, tk[4*i+1], s1);
            s2 = fmaf(v.z, tk[4*i+2], s2);
            s3 = fmaf(v.w, tk[4*i+3], s3);
        }
        float d = (s0 + s1) + (s2 + s3);
        if (d > bv) { bv = d; bi = c; }
    }
#pragma unroll
    for (int o = 16; o; o >>= 1) {
        float ov = __shfl_xor_sync(0xffffffffu, bv, o);
        int   oi = __shfl_xor_sync(0xffffffffu, bi, o);
        if (ov > bv || (ov == bv && oi < bi)) { bv = ov; bi = oi; }
    }
    if (lane == 0) {
        g_pv[(size_t)t * CS + blockIdx.y] = bv;
        g_pi[(size_t)t * CS + blockIdx.y] = bi;
    }
}

// ------- combine code-split partials (min-index tie-break) + optional hist -------
__global__ void k_combine(int ntok, int CS, int do_hist) {
    int t = blockIdx.x * 256 + threadIdx.x;
    if (t >= ntok) return;
    float bv = g_pv[(size_t)t * CS];
    int bi = g_pi[(size_t)t * CS];
    for (int cs = 1; cs < CS; cs++) {
        float v = g_pv[(size_t)t * CS + cs];
        int i = g_pi[(size_t)t * CS + cs];
        if (v > bv || (v == bv && i < bi)) { bv = v; bi = i; }
    }
    g_idx[t] = bi;
    if (do_hist) atomicAdd(&g_hist[bi], 1);
}

// -------- fused: gather codes -> bicubic upsample -> 3x3 conv (Phi) -> update --------
// one block per batch image b; 256 threads. smem = 111904 bytes.
#define SW_OFF   0
#define SB_OFF   9216
#define HUP_OFF  (9216+32)
#define HS_OFF   (HUP_OFF+10400)
#define WT_OFF   (HS_OFF+8192)
#define JT_OFF   (WT_OFF+64)
#define RED_OFF  (JT_OFF+64)
#define SMEM_FLOATS (RED_OFF+8)

__global__ __launch_bounds__(256) void k_fused(
    const float* __restrict__ fin, float* __restrict__ fhat,
    const float* __restrict__ cb, const float* __restrict__ phiw,
    const float* __restrict__ phib, int si, int pn, int k, int last) {
    extern __shared__ float sm[];
    float* s_w   = sm + SW_OFF;
    float* s_b   = sm + SB_OFF;
    float* s_hup = sm + HUP_OFF;   // [32][325] (18x18 halo, padded stride)
    float* s_hs  = sm + HS_OFF;    // [p][c]
    float* s_wt  = sm + WT_OFF;    // bicubic weights [16][4]
    int*   s_jt  = (int*)(sm + JT_OFF);
    float* s_red = sm + RED_OFF;

    int tid = threadIdx.x;
    int b = blockIdx.x;
    int pnpn = pn * pn;

    // load Phi weights/bias
    {
        const float4* wsrc = (const float4*)(phiw + (size_t)k * 9216);
        float4* wdst = (float4*)s_w;
        for (int i = tid; i < 2304; i += 256) wdst[i] = wsrc[i];
        if (tid < 32) s_b[tid] = phib[k * 32 + tid];
    }
    // zero halo image
    for (int i = tid; i < 10400; i += 256) s_hup[i] = 0.f;

    if (!last) {
        if (tid < 64) {
            int i = tid >> 2, off = (tid & 3) - 1;
            double src = (i + 0.5) * (double)pn / 16.0 - 0.5;
            double i0 = floor(src);
            double f = src - i0;
            double t = fabs(f - (double)off);
            double w;
            if (t <= 1.0)      w = (1.25 * t - 2.25) * t * t + 1.0;
            else if (t < 2.0)  w = (((t - 5.0) * t + 8.0) * t - 4.0) * (-0.75);
            else               w = 0.0;
            int j = (int)i0 + off;
            j = min(max(j, 0), pn - 1);
            s_wt[tid] = (float)w;
            s_jt[tid] = j;
        }
        for (int t = tid; t < pnpn * 32; t += 256) {
            int p = t >> 5, c = t & 31;
            s_hs[t] = cb[(size_t)g_idx[b * pnpn + p] * NC + c];
        }
    }
    __syncthreads();

    // build h_up (interior of halo'd image)
    if (last) {
        for (int o = tid; o < 8192; o += 256) {
            int c = o & 31, pix = o >> 5;
            int y = pix >> 4, x = pix & 15;
            s_hup[c * 325 + (y + 1) * 18 + (x + 1)] =
                cb[(size_t)g_idx[b * 256 + pix] * NC + c];
        }
    } else {
        for (int o = tid; o < 8192; o += 256) {
            int c = o & 31, pix = o >> 5;
            int y = pix >> 4, x = pix & 15;
            float acc = 0.f;
#pragma unroll
            for (int ty = 0; ty < 4; ty++) {
                float wy = s_wt[y * 4 + ty];
                int jy = s_jt[y * 4 + ty];
                const float* row = s_hs + (jy * pn) * 32 + c;
                float rs = 0.f;
#pragma unroll
                for (int tx = 0; tx < 4; tx++)
                    rs = fmaf(s_wt[x * 4 + tx], row[s_jt[x * 4 + tx] * 32], rs);
                acc = fmaf(wy, rs, acc);
            }
            s_hup[c * 325 + (y + 1) * 18 + (x + 1)] = acc;
        }
    }
    __syncthreads();

    // 3x3 conv: warp wi owns co in [4wi, 4wi+4); lane -> (y = lane>>1, xs = (lane&1)*8)
    int wi = tid >> 5, lane = tid & 31;
    int y = lane >> 1, xs = (lane & 1) * 8;
    float acc[4][8];
#pragma unroll
    for (int a = 0; a < 4; a++)
#pragma unroll
        for (int o = 0; o < 8; o++) acc[a][o] = 0.f;

    for (int ci = 0; ci < 32; ci++) {
        float tp[3][10];
        const float* hp = s_hup + ci * 325 + y * 18 + xs;
#pragma unroll
        for (int r = 0; r < 3; r++)
#pragma unroll
            for (int cc = 0; cc < 10; cc++) tp[r][cc] = hp[r * 18 + cc];
#pragma unroll
        for (int co4 = 0; co4 < 4; co4++) {
            const float* wp = s_w + ((size_t)(wi * 4 + co4) * 32 + ci) * 9;
            float w0 = wp[0], w1 = wp[1], w2 = wp[2];
            float w3 = wp[3], w4 = wp[4], w5 = wp[5];
            float w6 = wp[6], w7 = wp[7], w8 = wp[8];
#pragma unroll
            for (int xo = 0; xo < 8; xo++) {
                float s = acc[co4][xo];
                s = fmaf(w0, tp[0][xo],     s);
                s = fmaf(w1, tp[0][xo + 1], s);
                s = fmaf(w2, tp[0][xo + 2], s);
                s = fmaf(w3, tp[1][xo],     s);
                s = fmaf(w4, tp[1][xo + 1], s);
                s = fmaf(w5, tp[1][xo + 2], s);
                s = fmaf(w6, tp[2][xo],     s);
                s = fmaf(w7, tp[2][xo + 1], s);
                s = fmaf(w8, tp[2][xo + 2], s);
                acc[co4][xo] = s;
            }
        }
    }

    // h = 0.5*h_up + 0.5*(conv + bias); update f_hat, f_rest; accumulate MSE
    float sq = 0.f;
    const float* finb = fin + (size_t)b * 8192;
    float* fhb = fhat + (size_t)b * 8192;
    float* frb = g_frest + (size_t)b * 8192;
#pragma unroll
    for (int co4 = 0; co4 < 4; co4++) {
        int co = wi * 4 + co4;
        float bias = s_b[co];
#pragma unroll
        for (int xo = 0; xo < 8; xo++) {
            int x = xs + xo;
            float conv = acc[co4][xo] + bias;
            float hu = s_hup[co * 325 + (y + 1) * 18 + (x + 1)];
            float h = 0.5f * hu + 0.5f * conv;
            int g = co * 256 + y * 16 + x;
            float fh = fhb[g] + h;
            fhb[g] = fh;
            frb[g] = frb[g] - h;
            float d = fh - finb[g];
            sq = fmaf(d, d, sq);
        }
    }
#pragma unroll
    for (int o = 16; o; o >>= 1) sq += __shfl_down_sync(0xffffffffu, sq, o);
    if (lane == 0) s_red[wi] = sq;
    __syncthreads();
    if (tid == 0) {
        float s = 0.f;
        for (int i = 0; i < 8; i++) s += s_red[i];
        g_part[si * NB + b] = s;
    }
}

// ---------------- finalize: loss + perplexity ----------------
__global__ void k_final(float* __restrict__ out, int out_size) {
    __shared__ float sr[256];
    int tid = threadIdx.x;
    float s = 0.f;
    for (int i = tid; i < 10 * NB; i += 256) s += g_part[i];
    sr[tid] = s;
    __syncthreads();
    for (int o = 128; o; o >>= 1) {
        if (tid < o) sr[tid] += sr[tid + o];
        __syncthreads();
    }
    float lossv = 0.f;
    if (tid == 0) lossv = sr[0] * (1.25f / (10.0f * (float)FSZ));
    __syncthreads();

    float e = 0.f;
    for (int i = tid; i < NE; i += 256) {
        float p = (float)g_hist[i] * (1.0f / 32768.0f);
        e += p * logf(p + 1e-10f);
    }
    sr[tid] = e;
    __syncthreads();
    for (int o = 128; o; o >>= 1) {
        if (tid < o) sr[tid] += sr[tid + o];
        __syncthreads();
    }
    if (tid == 0) {
        out[out_size - 2] = lossv;
        out[out_size - 1] = expf(-sr[0]);
    }
}

// ---------------- launcher ----------------
extern "C" void kernel_launch(void* const* d_in, const int* in_sizes, int n_in,
                              void* d_out, int out_size) {
    // Identify inputs BY SIZE (robust to metadata ordering):
    //   f_input 1048576, codebook 131072, phi_w 36864, phi_b 128
    const float* fin  = nullptr;
    const float* cb   = nullptr;
    const float* phiw = nullptr;
    const float* phib = nullptr;
    for (int i = 0; i < n_in; i++) {
        int sz = in_sizes[i];
        if      (sz == FSZ)        fin  = (const float*)d_in[i];
        else if (sz == NE * NC)    cb   = (const float*)d_in[i];
        else if (sz == 4*NC*NC*9)  phiw = (const float*)d_in[i];
        else if (sz == 4*NC)       phib = (const float*)d_in[i];
    }
    float* out = (float*)d_out;

    // PhiPartiallyShared tick schedule, replicating numpy float64 exactly.
    int phik[10];
    {
        double start = 1.0 / 12.0;
        double stop  = 1.0 - 1.0 / 12.0;
        double step  = (stop - start) / 3.0;
        double ticks[4];
        ticks[0] = start;
        ticks[1] = 1.0 * step + start;
        ticks[2] = 2.0 * step + start;
        ticks[3] = stop;
        for (int si = 0; si < 10; si++) {
            double v = (double)si / 9.0;
            int best = 0;
            double bd = fabs(ticks[0] - v);
            for (int kk = 1; kk < 4; kk++) {
                double d = fabs(ticks[kk] - v);
                if (d < bd) { bd = d; best = kk; }
            }
            phik[si] = best;
        }
    }

    cudaFuncSetAttribute(k_fused, cudaFuncAttributeMaxDynamicSharedMemorySize,
                         SMEM_FLOATS * 4);

    int initN = (FSZ > out_size ? FSZ : out_size);
    k_init<<<(initN + 255) / 256, 256>>>(fin, out, out_size);
    k_cbnorm<<<(NE + 255) / 256, 256>>>(cb);

    for (int si = 0; si < 10; si++) {
        int pn = h_PNS[si];
        int ntok = NB * pn * pn;
        int last = (si == 9);

        k_down<<<(ntok * NC + 255) / 256, 256>>>(pn);

        int CS;
        if (ntok <= 1152) {
            // warp-per-token path (pn <= 3)
            int gx = (ntok + 3) / 4;
            CS = 1;
            while (gx * CS < 296 && CS < 32) CS <<= 1;
            dim3 g(gx, CS);
            k_argmax_small<<<g, 128>>>(ntok, NE / CS);
        } else {
            int tb = (ntok + 255) / 256;
            CS = 1;
            while (tb * CS < 296 && CS < 32) CS <<= 1;
            dim3 g(tb, CS);
            k_argmax<<<g, 128>>>(ntok, NE / CS);
        }
        k_combine<<<(ntok + 255) / 256, 256>>>(ntok, CS, last);

        k_fused<<<NB, 256, SMEM_FLOATS * 4>>>(fin, out, cb, phiw, phib,
                                              si, pn, phik[si], last);
    }
    k_final<<<1, 256>>>(out, out_size);
}

// round 5
// speedup vs baseline: 1.5855x; 1.1710x over previous
#include <cuda_runtime.h>
#include <cuda_bf16.h>
#include <math.h>

#define NB 128
#define NC 32
#define HW 16
#define NE 4096
#define FSZ (NB*NC*HW*HW)   // 1048576
#define PVCAP (256*1024)

typedef unsigned long long u64;

static const int h_PNS[10] = {1,2,3,4,5,6,8,10,13,16};

// ---------------- scratch (device globals; no allocation) ----------------
__device__ float g_cbn[NE*NC];        // normalized codebook
__device__ float g_frest[FSZ];        // residual
__device__ float g_x[FSZ];            // tokens [ntok][32]
__device__ float g_pv[PVCAP];         // partial argmax values
__device__ int   g_pi[PVCAP];         // partial argmax indices
__device__ int   g_hist[NE];          // last-scale histogram
__device__ float g_part[10*NB];       // per (scale, b) sum of squares

__device__ __forceinline__ u64 ffma2(u64 a, u64 b, u64 c) {
    u64 d; asm("fma.rn.f32x2 %0, %1, %2, %3;" : "=l"(d) : "l"(a), "l"(b), "l"(c));
    return d;
}
__device__ __forceinline__ u64 fadd2(u64 a, u64 b) {
    u64 d; asm("add.rn.f32x2 %0, %1, %2;" : "=l"(d) : "l"(a), "l"(b));
    return d;
}

// ---------------- init: f_rest <- f_input, zero out/hist ----------------
__global__ void k_init(const float* __restrict__ fin, float* __restrict__ out,
                       int out_size) {
    int i = blockIdx.x * 256 + threadIdx.x;
    if (i < FSZ) g_frest[i] = fin[i];
    if (i < NE)  g_hist[i] = 0;
    if (i < out_size) out[i] = 0.0f;
}

// ---------------- normalize codebook ----------------
__global__ void k_cbnorm(const float* __restrict__ cb) {
    int i = blockIdx.x * 256 + threadIdx.x;
    if (i >= NE) return;
    const float* r = cb + (size_t)i * NC;
    float s = 0.f;
#pragma unroll
    for (int c = 0; c < NC; c++) s += r[c] * r[c];
    float d = fmaxf(sqrtf(s), 1e-12f);
    float inv = 1.0f / d;
    float* w = g_cbn + (size_t)i * NC;
#pragma unroll
    for (int c = 0; c < NC; c++) w[c] = r[c] * inv;
}

// ---------------- area downsample f_rest -> tokens [ntok][C] ----------------
__global__ void k_down(int pn) {
    int t = blockIdx.x * 256 + threadIdx.x;
    int pnpn = pn * pn;
    int ntot = NB * pnpn * NC;
    if (t >= ntot) return;
    int c = t & 31, token = t >> 5;
    int b = token / pnpn, p = token - b * pnpn;
    int py = p / pn, px = p - py * pn;
    int ys = (py * HW) / pn, ye = ((py + 1) * HW + pn - 1) / pn;
    int xs = (px * HW) / pn, xe = ((px + 1) * HW + pn - 1) / pn;
    const float* base = g_frest + ((size_t)(b * NC + c)) * (HW * HW);
    float s = 0.f;
    for (int y = ys; y < ye; y++)
        for (int x = xs; x < xe; x++) s += base[y * HW + x];
    g_x[(size_t)token * NC + c] = s / (float)((ye - ys) * (xe - xs));
}

// ---------------- argmax: smem-tiled, T tokens per thread, f32x2 packed ----------
// grid = (ceil(ntok/(128*T)), CS), block = 128. cpb = 4096/CS (multiple of 128).
// pn16 != 0: read tokens transposed from g_frest (last scale, no k_down needed).
template<int T>
__global__ __launch_bounds__(128) void k_argmax_t(int ntok, int cpb, int pn16) {
    __shared__ float s_cb[128 * NC];
    int tid = threadIdx.x;
    int cbase = blockIdx.y * cpb;
    int tokbase = blockIdx.x * (128 * T) + tid;

    u64 tk[T][16];
    float bv[T]; int bi[T]; bool vld[T];
#pragma unroll
    for (int t = 0; t < T; t++) {
        int tok = tokbase + t * 128;
        vld[t] = tok < ntok;
        bv[t] = -3.4e38f; bi[t] = cbase;
#pragma unroll
        for (int i = 0; i < 16; i++) tk[t][i] = 0ULL;
        if (vld[t]) {
            if (pn16) {
                int b = tok >> 8, pix = tok & 255;
                const float* fr = g_frest + (size_t)b * 8192 + pix;
#pragma unroll
                for (int i = 0; i < 16; i++) {
                    float2 v;
                    v.x = fr[(2 * i) * 256];
                    v.y = fr[(2 * i + 1) * 256];
                    tk[t][i] = *(u64*)&v;
                }
            } else {
                const ulonglong2* p = (const ulonglong2*)(g_x + (size_t)tok * NC);
#pragma unroll
                for (int i = 0; i < 8; i++) {
                    ulonglong2 v = p[i];
                    tk[t][2 * i] = v.x; tk[t][2 * i + 1] = v.y;
                }
            }
        }
    }

    for (int tile = 0; tile < cpb; tile += 128) {
        __syncthreads();
        {
            const float4* src = (const float4*)(g_cbn + (size_t)(cbase + tile) * NC);
            float4* dst = (float4*)s_cb;
#pragma unroll
            for (int i = 0; i < 8; i++) dst[tid + i * 128] = src[tid + i * 128];
        }
        __syncthreads();
        for (int j = 0; j < 128; j++) {
            const ulonglong2* cr = (const ulonglong2*)(s_cb + j * NC);
            u64 c[16];
#pragma unroll
            for (int i = 0; i < 8; i++) {
                ulonglong2 v = cr[i];
                c[2 * i] = v.x; c[2 * i + 1] = v.y;
            }
            int code = cbase + tile + j;
#pragma unroll
            for (int t = 0; t < T; t++) {
                u64 p0 = 0ULL, p1 = 0ULL;
#pragma unroll
                for (int i = 0; i < 8; i++) {
                    p0 = ffma2(c[2 * i],     tk[t][2 * i],     p0);
                    p1 = ffma2(c[2 * i + 1], tk[t][2 * i + 1], p1);
                }
                u64 ps = fadd2(p0, p1);
                float2 pf = *(float2*)&ps;
                float d = pf.x + pf.y;
                if (d > bv[t]) { bv[t] = d; bi[t] = code; }
            }
        }
    }
    int CS = gridDim.y, cs = blockIdx.y;
#pragma unroll
    for (int t = 0; t < T; t++) {
        int tok = tokbase + t * 128;
        if (vld[t]) {
            g_pv[(size_t)tok * CS + cs] = bv[t];
            g_pi[(size_t)tok * CS + cs] = bi[t];
        }
    }
}

// -------- fused: combine partials -> gather codes -> bicubic up -> 3x3 conv -> update --
// one block per batch image b; 256 threads.
#define SW_OFF   0
#define SB_OFF   9216
#define HUP_OFF  (9216+32)
#define HS_OFF   (HUP_OFF+10400)
#define WT_OFF   (HS_OFF+8192)
#define JT_OFF   (WT_OFF+64)
#define RED_OFF  (JT_OFF+64)
#define IDX_OFF  (RED_OFF+8)
#define SMEM_FLOATS (IDX_OFF+256)

__global__ __launch_bounds__(256) void k_fused(
    const float* __restrict__ fin, float* __restrict__ fhat,
    const float* __restrict__ cb, const float* __restrict__ phiw,
    const float* __restrict__ phib, int si, int pn, int k, int last, int CS) {
    extern __shared__ float sm[];
    float* s_w   = sm + SW_OFF;
    float* s_b   = sm + SB_OFF;
    float* s_hup = sm + HUP_OFF;   // [32][325] (18x18 halo, padded stride)
    float* s_hs  = sm + HS_OFF;    // [p][c]
    float* s_wt  = sm + WT_OFF;    // bicubic weights [16][4]
    int*   s_jt  = (int*)(sm + JT_OFF);
    float* s_red = sm + RED_OFF;
    int*   s_idx = (int*)(sm + IDX_OFF);

    int tid = threadIdx.x;
    int b = blockIdx.x;
    int pnpn = pn * pn;

    // combine code-split argmax partials for this image's tokens (+ histogram)
    for (int p = tid; p < pnpn; p += 256) {
        size_t tb = (size_t)(b * pnpn + p) * CS;
        float bvv = g_pv[tb]; int bii = g_pi[tb];
        for (int cs = 1; cs < CS; cs++) {
            float v = g_pv[tb + cs]; int i2 = g_pi[tb + cs];
            if (v > bvv || (v == bvv && i2 < bii)) { bvv = v; bii = i2; }
        }
        s_idx[p] = bii;
        if (last) atomicAdd(&g_hist[bii], 1);
    }

    // load Phi weights/bias
    {
        const float4* wsrc = (const float4*)(phiw + (size_t)k * 9216);
        float4* wdst = (float4*)s_w;
        for (int i = tid; i < 2304; i += 256) wdst[i] = wsrc[i];
        if (tid < 32) s_b[tid] = phib[k * 32 + tid];
    }
    // zero halo image
    for (int i = tid; i < 10400; i += 256) s_hup[i] = 0.f;

    if (!last && tid < 64) {
        int i = tid >> 2, off = (tid & 3) - 1;
        double src = (i + 0.5) * (double)pn / 16.0 - 0.5;
        double i0 = floor(src);
        double f = src - i0;
        double t = fabs(f - (double)off);
        double w;
        if (t <= 1.0)      w = (1.25 * t - 2.25) * t * t + 1.0;
        else if (t < 2.0)  w = (((t - 5.0) * t + 8.0) * t - 4.0) * (-0.75);
        else               w = 0.0;
        int j = (int)i0 + off;
        j = min(max(j, 0), pn - 1);
        s_wt[tid] = (float)w;
        s_jt[tid] = j;
    }
    __syncthreads();

    if (!last) {
        for (int t = tid; t < pnpn * 32; t += 256) {
            int p = t >> 5, c = t & 31;
            s_hs[t] = cb[(size_t)s_idx[p] * NC + c];
        }
        __syncthreads();
    }

    // build h_up (interior of halo'd image)
    if (last) {
        for (int o = tid; o < 8192; o += 256) {
            int c = o & 31, pix = o >> 5;
            int y = pix >> 4, x = pix & 15;
            s_hup[c * 325 + (y + 1) * 18 + (x + 1)] =
                cb[(size_t)s_idx[pix] * NC + c];
        }
    } else {
        for (int o = tid; o < 8192; o += 256) {
            int c = o & 31, pix = o >> 5;
            int y = pix >> 4, x = pix & 15;
            float acc = 0.f;
#pragma unroll
            for (int ty = 0; ty < 4; ty++) {
                float wy = s_wt[y * 4 + ty];
                int jy = s_jt[y * 4 + ty];
                const float* row = s_hs + (jy * pn) * 32 + c;
                float rs = 0.f;
#pragma unroll
                for (int tx = 0; tx < 4; tx++)
                    rs = fmaf(s_wt[x * 4 + tx], row[s_jt[x * 4 + tx] * 32], rs);
                acc = fmaf(wy, rs, acc);
            }
            s_hup[c * 325 + (y + 1) * 18 + (x + 1)] = acc;
        }
    }
    __syncthreads();

    // 3x3 conv: warp wi owns co in [4wi, 4wi+4); lane -> (y = lane>>1, xs = (lane&1)*8)
    int wi = tid >> 5, lane = tid & 31;
    int y = lane >> 1, xs = (lane & 1) * 8;
    float acc[4][8];
#pragma unroll
    for (int a = 0; a < 4; a++)
#pragma unroll
        for (int o = 0; o < 8; o++) acc[a][o] = 0.f;

    for (int ci = 0; ci < 32; ci++) {
        float tp[3][10];
        const float* hp = s_hup + ci * 325 + y * 18 + xs;
#pragma unroll
        for (int r = 0; r < 3; r++)
#pragma unroll
            for (int cc = 0; cc < 10; cc++) tp[r][cc] = hp[r * 18 + cc];
#pragma unroll
        for (int co4 = 0; co4 < 4; co4++) {
            const float* wp = s_w + ((size_t)(wi * 4 + co4) * 32 + ci) * 9;
            float w0 = wp[0], w1 = wp[1], w2 = wp[2];
            float w3 = wp[3], w4 = wp[4], w5 = wp[5];
            float w6 = wp[6], w7 = wp[7], w8 = wp[8];
#pragma unroll
            for (int xo = 0; xo < 8; xo++) {
                float s = acc[co4][xo];
                s = fmaf(w0, tp[0][xo],     s);
                s = fmaf(w1, tp[0][xo + 1], s);
                s = fmaf(w2, tp[0][xo + 2], s);
                s = fmaf(w3, tp[1][xo],     s);
                s = fmaf(w4, tp[1][xo + 1], s);
                s = fmaf(w5, tp[1][xo + 2], s);
                s = fmaf(w6, tp[2][xo],     s);
                s = fmaf(w7, tp[2][xo + 1], s);
                s = fmaf(w8, tp[2][xo + 2], s);
                acc[co4][xo] = s;
            }
        }
    }

    // h = 0.5*h_up + 0.5*(conv + bias); update f_hat, f_rest; accumulate MSE
    float sq = 0.f;
    const float* finb = fin + (size_t)b * 8192;
    float* fhb = fhat + (size_t)b * 8192;
    float* frb = g_frest + (size_t)b * 8192;
#pragma unroll
    for (int co4 = 0; co4 < 4; co4++) {
        int co = wi * 4 + co4;
        float bias = s_b[co];
#pragma unroll
        for (int xo = 0; xo < 8; xo++) {
            int x = xs + xo;
            float conv = acc[co4][xo] + bias;
            float hu = s_hup[co * 325 + (y + 1) * 18 + (x + 1)];
            float h = 0.5f * hu + 0.5f * conv;
            int g = co * 256 + y * 16 + x;
            float fh = fhb[g] + h;
            fhb[g] = fh;
            frb[g] = frb[g] - h;
            float d = fh - finb[g];
            sq = fmaf(d, d, sq);
        }
    }
#pragma unroll
    for (int o = 16; o; o >>= 1) sq += __shfl_down_sync(0xffffffffu, sq, o);
    if (lane == 0) s_red[wi] = sq;
    __syncthreads();
    if (tid == 0) {
        float s = 0.f;
        for (int i = 0; i < 8; i++) s += s_red[i];
        g_part[si * NB + b] = s;
    }
}

// ---------------- finalize: loss + perplexity ----------------
__global__ void k_final(float* __restrict__ out, int out_size) {
    __shared__ float sr[256];
    int tid = threadIdx.x;
    float s = 0.f;
    for (int i = tid; i < 10 * NB; i += 256) s += g_part[i];
    sr[tid] = s;
    __syncthreads();
    for (int o = 128; o; o >>= 1) {
        if (tid < o) sr[tid] += sr[tid + o];
        __syncthreads();
    }
    float lossv = 0.f;
    if (tid == 0) lossv = sr[0] * (1.25f / (10.0f * (float)FSZ));
    __syncthreads();

    float e = 0.f;
    for (int i = tid; i < NE; i += 256) {
        float p = (float)g_hist[i] * (1.0f / 32768.0f);
        e += p * logf(p + 1e-10f);
    }
    sr[tid] = e;
    __syncthreads();
    for (int o = 128; o; o >>= 1) {
        if (tid < o) sr[tid] += sr[tid + o];
        __syncthreads();
    }
    if (tid == 0) {
        out[out_size - 2] = lossv;
        out[out_size - 1] = expf(-sr[0]);
    }
}

// ---------------- launcher ----------------
extern "C" void kernel_launch(void* const* d_in, const int* in_sizes, int n_in,
                              void* d_out, int out_size) {
    // Identify inputs BY SIZE (robust to metadata ordering):
    //   f_input 1048576, codebook 131072, phi_w 36864, phi_b 128
    const float* fin  = nullptr;
    const float* cb   = nullptr;
    const float* phiw = nullptr;
    const float* phib = nullptr;
    for (int i = 0; i < n_in; i++) {
        int sz = in_sizes[i];
        if      (sz == FSZ)        fin  = (const float*)d_in[i];
        else if (sz == NE * NC)    cb   = (const float*)d_in[i];
        else if (sz == 4*NC*NC*9)  phiw = (const float*)d_in[i];
        else if (sz == 4*NC)       phib = (const float*)d_in[i];
    }
    float* out = (float*)d_out;

    // PhiPartiallyShared tick schedule, replicating numpy float64 exactly.
    int phik[10];
    {
        double start = 1.0 / 12.0;
        double stop  = 1.0 - 1.0 / 12.0;
        double step  = (stop - start) / 3.0;
        double ticks[4];
        ticks[0] = start;
        ticks[1] = 1.0 * step + start;
        ticks[2] = 2.0 * step + start;
        ticks[3] = stop;
        for (int si = 0; si < 10; si++) {
            double v = (double)si / 9.0;
            int best = 0;
            double bd = fabs(ticks[0] - v);
            for (int kk = 1; kk < 4; kk++) {
                double d = fabs(ticks[kk] - v);
                if (d < bd) { bd = d; best = kk; }
            }
            phik[si] = best;
        }
    }

    cudaFuncSetAttribute(k_fused, cudaFuncAttributeMaxDynamicSharedMemorySize,
                         SMEM_FLOATS * 4);

    int initN = (FSZ > out_size ? FSZ : out_size);
    k_init<<<(initN + 255) / 256, 256>>>(fin, out, out_size);
    k_cbnorm<<<(NE + 255) / 256, 256>>>(cb);

    for (int si = 0; si < 10; si++) {
        int pn = h_PNS[si];
        int ntok = NB * pn * pn;
        int last = (si == 9);

        if (!last) k_down<<<(ntok * NC + 255) / 256, 256>>>(pn);

        int CS;
        if (ntok >= 4608) {
            // T = 4 tokens/thread: 512 tokens per block
            int tb = (ntok + 511) / 512;
            CS = 1;
            while (tb * CS < 296 && CS < 32) CS <<= 1;
            dim3 g(tb, CS);
            k_argmax_t<4><<<g, 128>>>(ntok, NE / CS, last ? 1 : 0);
        } else {
            // T = 1 token/thread: 128 tokens per block
            int tb = ntok / 128;
            CS = 1;
            while (tb * CS < 296 && CS < 32) CS <<= 1;
            dim3 g(tb, CS);
            k_argmax_t<1><<<g, 128>>>(ntok, NE / CS, 0);
        }

        k_fused<<<NB, 256, SMEM_FLOATS * 4>>>(fin, out, cb, phiw, phib,
                                              si, pn, phik[si], last, CS);
    }
    k_final<<<1, 256>>>(out, out_size);
}